// round 9
// baseline (speedup 1.0000x reference)
#include <cuda_runtime.h>
#include <cuda_bf16.h>
#include <math.h>

// Box-embedding conditional-probability loss. B pairs, D=128.
// R9: R8's cp.async pipeline showed 2.7x per-warp issue efficiency vs direct
// LDG but stalled on prefetch distance 1 (one compute iter < DRAM latency).
// Deepen: TRIPLE buffer, prefetch distance 2 (cp_wait<2>), 8 stages/warp.
// 4 warps/block x 24KB = 96KB/block -> 2 blocks/SM = 8 warps/SM.

#define EPS_F 1e-8f

#define WARPS_PER_BLOCK 4
#define G_PER_WARP      8          // stages (pair-groups) per warp
#define PAIRS_PER_GROUP 4
#define NBUF            3          // triple buffer, prefetch distance 2
#define ROW_BYTES       512        // one table row: 128 fp32
#define STAGE_BYTES     (PAIRS_PER_GROUP * 4 * ROW_BYTES)   // 8192
#define WARP_SMEM       (NBUF * STAGE_BYTES)                // 24576
#define BLOCK_SMEM      (WARPS_PER_BLOCK * WARP_SMEM)       // 98304

static __device__ __forceinline__ void cp_async16(unsigned int dst, const void* src) {
    asm volatile("cp.async.cg.shared.global [%0], [%1], 16;\n"
                 :: "r"(dst), "l"(src));
}
static __device__ __forceinline__ void cp_commit() {
    asm volatile("cp.async.commit_group;\n" ::: "memory");
}
template <int N>
static __device__ __forceinline__ void cp_wait() {
    asm volatile("cp.async.wait_group %0;\n" :: "n"(N) : "memory");
}

static __device__ __forceinline__ float split_mant(float p, int& e) {
    int ib = __float_as_int(p);
    e += ((ib >> 23) & 0xFF) - 127;
    return __int_as_float((ib & 0x007FFFFF) | 0x3F800000);  // [1,2)
}

__global__ void __launch_bounds__(WARPS_PER_BLOCK * 32)
box_pair_kernel(const int* __restrict__ t1x,
                const int* __restrict__ t2x,
                const float* __restrict__ min_tab,
                const float* __restrict__ dlt_tab,
                float* __restrict__ out_pos,
                float* __restrict__ out_neg,
                int B)
{
    extern __shared__ char smem[];

    const float MIN_MEAN   = (float)((0.0001 + 0.01) / 2.0);
    const float MIN_VAR    = (float)(0.01 - (0.0001 + 0.01) / 2.0);
    const float DELTA_MEAN = (float)((0.9 + 0.999) / 2.0);
    const float DELTA_VAR  = (float)(0.999 - (0.9 + 0.999) / 2.0);
    const unsigned int FULL = 0xFFFFFFFFu;

    int warpid = threadIdx.x >> 5;
    int lane   = threadIdx.x & 31;
    int sub    = lane & 7;          // lane within 8-lane pair group
    int g      = lane >> 3;         // pair group 0..3 (compute phase)

    int wglob  = blockIdx.x * WARPS_PER_BLOCK + warpid;   // global warp id

    char* wsmem = smem + warpid * WARP_SMEM;
    unsigned int wsaddr = (unsigned int)__cvta_generic_to_shared(wsmem);

    // ---- prefetch stage `it` into buffer `buf`: 16 rows x 512B --------
    // Always commits exactly one group (possibly empty) for uniform
    // group accounting with cp_wait<2>.
    auto prefetch = [&](int it, int buf) {
        if (it >= G_PER_WARP) { cp_commit(); return; }
        int pb = (wglob * G_PER_WARP + it) * PAIRS_PER_GROUP;  // pair base
        if (pb >= B) { cp_commit(); return; }
        int pidx = pb + (lane & 3);
        if (pidx >= B) pidx = B - 1;
        int i1v = __ldg(t1x + pidx);
        int i2v = __ldg(t2x + pidx);
        unsigned int dst = wsaddr + buf * STAGE_BYTES + lane * 16;
#pragma unroll
        for (int r = 0; r < 16; r++) {
            int p = r >> 2;                               // pair in group
            int tok = __shfl_sync(FULL, (r & 2) ? i2v : i1v, p);
            const float* tab = (r & 1) ? dlt_tab : min_tab;
            cp_async16(dst + r * ROW_BYTES,
                       tab + (size_t)tok * 128 + lane * 4);
        }
        cp_commit();
    };

    prefetch(0, 0);
    prefetch(1, 1);

    int buf = 0;
    for (int it = 0; it < G_PER_WARP; it++) {
        prefetch(it + 2, (buf + 2 == NBUF) ? 0 : ((buf + 2 > NBUF) ? buf - 1 : buf + 2));
        // note: (it+2)%3 == (buf+2)%3; expression avoids slow modulo
        cp_wait<2>();              // stage `it` complete; 2 newer in flight
        __syncwarp();              // all lanes' copies visible to all lanes

        int pb   = (wglob * G_PER_WARP + it) * PAIRS_PER_GROUP;
        int pair = pb + g;
        bool live = (pair < B);

        // my pair's 4 rows: m1,d1,m2,d2 at +0,+512,+1024,+1536
        const char* pbase = wsmem + buf * STAGE_BYTES + g * 2048 + sub * 16;

        float p1 = 1.0f, p2 = 1.0f, pm = 1.0f, pj = 1.0f;
        float mr = 3.4e38f;

#pragma unroll
        for (int c = 0; c < 4; c++) {
            float4 m1 = *(const float4*)(pbase +    0 + c * 128);
            float4 d1 = *(const float4*)(pbase +  512 + c * 128);
            float4 m2 = *(const float4*)(pbase + 1024 + c * 128);
            float4 d2 = *(const float4*)(pbase + 1536 + c * 128);

            const float* m1v = &m1.x;
            const float* d1v = &d1.x;
            const float* m2v = &m2.x;
            const float* d2v = &d2.x;
#pragma unroll
            for (int j = 0; j < 4; j++) {
                float a  = fmaf(m1v[j], MIN_VAR, MIN_MEAN);
                float da = fmaf(d1v[j], DELTA_VAR, DELTA_MEAN);
                float c0 = fmaf(m2v[j], MIN_VAR, MIN_MEAN);
                float dc = fmaf(d2v[j], DELTA_VAR, DELTA_MEAN);
                float b  = a + da;
                float d  = c0 + dc;

                float jmin = fminf(a, c0);
                float jmax = fmaxf(b, d);
                float ej   = jmax - jmin;       // join extent
                float em   = (da + dc) - ej;    // meet extent (min+max=sum)

                mr = fminf(mr, em);
                p1 *= da;
                p2 *= dc;
                pj *= ej;
                pm *= em;   // clamp dropped: em<=0 only in disjoint branch,
                            // where pm is discarded
            }
        }

        int EM = 0;
        pm = split_mant(pm, EM);   // keep cross-lane meet product fp32-safe

        float rm = __fdividef(pm, p2);   // -> meet_log - t2_log
        float rj = __fdividef(pj, p1);   // -> join_log - t1_log

#pragma unroll
        for (int off = 4; off > 0; off >>= 1) {
            rm *= __shfl_xor_sync(FULL, rm, off);
            rj *= __shfl_xor_sync(FULL, rj, off);
            EM += __shfl_xor_sync(FULL, EM, off);
        }

        unsigned int ball = __ballot_sync(FULL, mr <= 0.0f);
        bool disjoint = ((ball >> (lane & 24)) & 0xFFu) != 0u;

        if (sub == 0 && live) {
            const float LN2 = 0.69314718055994530942f;
            float posv, negv;
            if (disjoint) {
                posv = logf(rj);
                negv = 0.0f;
            } else {
                float cond = logf(rm) + (float)EM * LN2;  // log P(t1|t2)
                posv = -cond;
                negv = -logf(fmaxf(1.0f - expf(cond), EPS_F));
            }
            out_pos[pair] = posv;
            out_neg[pair] = negv;
        }
        __syncwarp();   // reads done before this buffer is overwritten

        buf = (buf + 1 == NBUF) ? 0 : buf + 1;
    }
}

extern "C" void kernel_launch(void* const* d_in, const int* in_sizes, int n_in,
                              void* d_out, int out_size) {
    const int*   t1x    = (const int*)d_in[0];
    const int*   t2x    = (const int*)d_in[1];
    const float* min_tb = (const float*)d_in[2];
    const float* dlt_tb = (const float*)d_in[3];

    int B = in_sizes[0];
    float* out_pos = (float*)d_out;
    float* out_neg = (float*)d_out + B;

    static int configured = 0;
    if (!configured) {
        cudaFuncSetAttribute(box_pair_kernel,
                             cudaFuncAttributeMaxDynamicSharedMemorySize,
                             BLOCK_SMEM);
        cudaFuncSetAttribute(box_pair_kernel,
                             cudaFuncAttributePreferredSharedMemoryCarveout,
                             100);
        configured = 1;
    }

    int pairs_per_block = WARPS_PER_BLOCK * G_PER_WARP * PAIRS_PER_GROUP; // 128
    int grid = (B + pairs_per_block - 1) / pairs_per_block;
    box_pair_kernel<<<grid, WARPS_PER_BLOCK * 32, BLOCK_SMEM>>>(
        t1x, t2x, min_tb, dlt_tb, out_pos, out_neg, B);
}

// round 10
// speedup vs baseline: 1.5722x; 1.5722x over previous
#include <cuda_runtime.h>
#include <cuda_bf16.h>
#include <math.h>

// Box-embedding conditional-probability loss. B pairs, D=128.
// R10: R4 frame (8 lanes/pair, 32 regs, 85% occ — best at 27.4us) measured
// at ~85% of the practical LTS cap (~9.8 of ~11-12 TB/s). Shave the rest:
//  - __ldcs (evict-first) table reads: no reuse -> don't thrash L1D.
//  - drop per-dim meet clamp (only binds when disjoint, where pm is unused)
//    and per-chunk renorm (single per-lane split; products in [1e-5,70]).

#define EPS_F 1e-8f

static __device__ __forceinline__ float split_mant(float p, int& e) {
    int ib = __float_as_int(p);
    e += ((ib >> 23) & 0xFF) - 127;
    return __int_as_float((ib & 0x007FFFFF) | 0x3F800000);  // [1,2)
}

__global__ void __launch_bounds__(256, 8)
box_pair_kernel(const int* __restrict__ t1x,
                const int* __restrict__ t2x,
                const float* __restrict__ min_tab,
                const float* __restrict__ dlt_tab,
                float* __restrict__ out_pos,
                float* __restrict__ out_neg,
                int B)
{
    const float MIN_MEAN   = (float)((0.0001 + 0.01) / 2.0);
    const float MIN_VAR    = (float)(0.01 - (0.0001 + 0.01) / 2.0);
    const float DELTA_MEAN = (float)((0.9 + 0.999) / 2.0);
    const float DELTA_VAR  = (float)(0.999 - (0.9 + 0.999) / 2.0);

    int gtid = blockIdx.x * blockDim.x + threadIdx.x;
    int pair = gtid >> 3;           // 8 lanes per pair
    int sub  = threadIdx.x & 7;
    if (pair >= B) return;

    int i1 = __ldg(t1x + pair);
    int i2 = __ldg(t2x + pair);

    const float4* m1p = (const float4*)(min_tab + (size_t)i1 * 128) + sub;
    const float4* d1p = (const float4*)(dlt_tab + (size_t)i1 * 128) + sub;
    const float4* m2p = (const float4*)(min_tab + (size_t)i2 * 128) + sub;
    const float4* d2p = (const float4*)(dlt_tab + (size_t)i2 * 128) + sub;

    float p1 = 1.0f, p2 = 1.0f, pm = 1.0f, pj = 1.0f;
    float mr = 3.4e38f;   // min raw meet extent over my dims

#pragma unroll
    for (int c = 0; c < 4; c++) {
        // streaming loads: gather data has ~1% reuse -> bypass L1 allocation
        float4 m1 = __ldcs(m1p + c * 8);
        float4 d1 = __ldcs(d1p + c * 8);
        float4 m2 = __ldcs(m2p + c * 8);
        float4 d2 = __ldcs(d2p + c * 8);

        const float* m1v = &m1.x;
        const float* d1v = &d1.x;
        const float* m2v = &m2.x;
        const float* d2v = &d2.x;

#pragma unroll
        for (int j = 0; j < 4; j++) {
            float a  = fmaf(m1v[j], MIN_VAR, MIN_MEAN);     // t1_min
            float da = fmaf(d1v[j], DELTA_VAR, DELTA_MEAN); // t1 extent
            float c0 = fmaf(m2v[j], MIN_VAR, MIN_MEAN);     // t2_min
            float dc = fmaf(d2v[j], DELTA_VAR, DELTA_MEAN); // t2 extent
            float b  = a + da;                              // t1_max
            float d  = c0 + dc;                             // t2_max

            float jmin = fminf(a, c0);
            float jmax = fmaxf(b, d);
            float ej   = jmax - jmin;                 // join extent
            float em   = (da + dc) - ej;              // meet extent (identity)

            mr = fminf(mr, em);
            p1 *= da;
            p2 *= dc;
            pj *= ej;
            pm *= em;   // clamp dropped: em<=0 only when disjoint, where
                        // pm is discarded by the output branch
        }
    }

    // single per-lane renorm keeps the cross-lane meet product fp32-safe
    int EM = 0;
    pm = split_mant(pm, EM);

    // ratios: outputs only need (meet - t2) and (join - t1) log-differences
    float rm = __fdividef(pm, p2);
    float rj = __fdividef(pj, p1);

    const unsigned int FULL = 0xFFFFFFFFu;
#pragma unroll
    for (int off = 4; off > 0; off >>= 1) {
        rm *= __shfl_xor_sync(FULL, rm, off);
        rj *= __shfl_xor_sync(FULL, rj, off);
        EM += __shfl_xor_sync(FULL, EM, off);
    }

    // disjoint = any lane in my 8-lane group saw em <= 0
    unsigned int ball = __ballot_sync(FULL, mr <= 0.0f);
    bool disjoint = ((ball >> (threadIdx.x & 24)) & 0xFFu) != 0u;

    if (sub == 0) {
        const float LN2 = 0.69314718055994530942f;
        float posv, negv;
        if (disjoint) {
            posv = logf(rj);                       // join_log - t1_log
            negv = 0.0f;
        } else {
            float cond = logf(rm) + (float)EM * LN2;   // log P(t1|t2)
            posv = -cond;
            negv = -logf(fmaxf(1.0f - expf(cond), EPS_F));
        }
        out_pos[pair] = posv;
        out_neg[pair] = negv;
    }
}

extern "C" void kernel_launch(void* const* d_in, const int* in_sizes, int n_in,
                              void* d_out, int out_size) {
    const int*   t1x    = (const int*)d_in[0];
    const int*   t2x    = (const int*)d_in[1];
    const float* min_tb = (const float*)d_in[2];
    const float* dlt_tb = (const float*)d_in[3];

    int B = in_sizes[0];
    float* out_pos = (float*)d_out;
    float* out_neg = (float*)d_out + B;

    // 8 lanes per pair, 32 pairs per 256-thread block
    int pairs_per_block = 32;
    int grid = (B + pairs_per_block - 1) / pairs_per_block;
    box_pair_kernel<<<grid, 256>>>(t1x, t2x, min_tb, dlt_tb, out_pos, out_neg, B);
}